// round 1
// baseline (speedup 1.0000x reference)
#include <cuda_runtime.h>
#include <cstdint>

#define Bdim 64
#define Tdim 512
#define Idim 512
#define Hdim 1024
#define Gdim 4096

typedef unsigned long long ull;

// Scratch (allocation-free rule: __device__ globals)
__device__ float g_gates_x[(size_t)Tdim * Bdim * Gdim];  // [t][b][g], 512 MB
__device__ float g_h[2][Bdim * Hdim];                    // ping-pong hidden state
__device__ float g_c[Bdim * Hdim];

// ---------------- packed f32x2 helpers (full-rate fp32 FMA on sm_103a) ----------
__device__ __forceinline__ ull pack2(float x, float y) {
    ull r; asm("mov.b64 %0, {%1,%2};" : "=l"(r) : "f"(x), "f"(y)); return r;
}
__device__ __forceinline__ void unpack2(ull v, float& x, float& y) {
    asm("mov.b64 {%0,%1}, %2;" : "=f"(x), "=f"(y) : "l"(v));
}
__device__ __forceinline__ void ffma2(ull& d, ull a, ull b) {
    asm("fma.rn.f32x2 %0, %1, %2, %0;" : "+l"(d) : "l"(a), "l"(b));
}

__device__ __forceinline__ float sigmoidf_(float x) {
    return 1.0f / (1.0f + __expf(-x));
}

// ---------------- init: zero state + output ------------------------------------
__global__ void init_state(float* __restrict__ out) {
    int i = blockIdx.x * blockDim.x + threadIdx.x;  // 65536 threads
    g_h[0][i] = 0.0f;
    g_h[1][i] = 0.0f;
    g_c[i] = 0.0f;
    out[i] = 0.0f;
}

// ---------------- GEMM1: gates_x[t][b][g] = seq @ W_ih^T + (b_ih+b_hh) ----------
// M = B*T = 32768 (m = b*T + t), N = 4096, K = 512. 128x128 tile, BK=8,
// 256 threads, 8x8 per-thread microtile with f32x2-packed columns.
__global__ __launch_bounds__(256) void gates_x_gemm(
    const float* __restrict__ seq, const float* __restrict__ Wih,
    const float* __restrict__ bih, const float* __restrict__ bhh) {
    __shared__ float As[8][132];
    __shared__ float Bs[8][132];

    const int tid = threadIdx.x;
    const int tx = tid & 15;          // 0..15 -> n microtile
    const int ty = tid >> 4;          // 0..15 -> m microtile
    const int m0 = blockIdx.y * 128;
    const int n0 = blockIdx.x * 128;

    const int lr = tid >> 1;          // 0..127 row to load
    const int lk = (tid & 1) * 4;     // 0 or 4 (float4 within BK=8)
    const float* aptr = seq + (size_t)(m0 + lr) * Idim + lk;
    const float* bptr = Wih + (size_t)(n0 + lr) * Idim + lk;

    ull acc[8][4];
#pragma unroll
    for (int i = 0; i < 8; i++)
#pragma unroll
        for (int j = 0; j < 4; j++) acc[i][j] = 0ull;

    for (int k0 = 0; k0 < Idim; k0 += 8) {
        float4 av = *(const float4*)(aptr + k0);
        float4 bv = *(const float4*)(bptr + k0);
        As[lk + 0][lr] = av.x; As[lk + 1][lr] = av.y;
        As[lk + 2][lr] = av.z; As[lk + 3][lr] = av.w;
        Bs[lk + 0][lr] = bv.x; Bs[lk + 1][lr] = bv.y;
        Bs[lk + 2][lr] = bv.z; Bs[lk + 3][lr] = bv.w;
        __syncthreads();
#pragma unroll
        for (int k = 0; k < 8; k++) {
            float4 a0 = *(const float4*)&As[k][ty * 8];
            float4 a1 = *(const float4*)&As[k][ty * 8 + 4];
            ull pb0 = *(const ull*)&Bs[k][tx * 8 + 0];
            ull pb1 = *(const ull*)&Bs[k][tx * 8 + 2];
            ull pb2 = *(const ull*)&Bs[k][tx * 8 + 4];
            ull pb3 = *(const ull*)&Bs[k][tx * 8 + 6];
            float am[8] = {a0.x, a0.y, a0.z, a0.w, a1.x, a1.y, a1.z, a1.w};
#pragma unroll
            for (int i = 0; i < 8; i++) {
                ull pa = pack2(am[i], am[i]);
                ffma2(acc[i][0], pa, pb0);
                ffma2(acc[i][1], pa, pb1);
                ffma2(acc[i][2], pa, pb2);
                ffma2(acc[i][3], pa, pb3);
            }
        }
        __syncthreads();
    }

#pragma unroll
    for (int i = 0; i < 8; i++) {
        int m = m0 + ty * 8 + i;
        int b = m >> 9;        // T = 512
        int t = m & 511;
        float* orow = g_gates_x + (size_t)(t * Bdim + b) * Gdim;
#pragma unroll
        for (int j = 0; j < 4; j++) {
            int n = n0 + tx * 8 + j * 2;
            float x, y; unpack2(acc[i][j], x, y);
            orow[n]     = x + bih[n]     + bhh[n];
            orow[n + 1] = y + bih[n + 1] + bhh[n + 1];
        }
    }
}

// ---------------- per-step fused kernel ----------------------------------------
// grid = 128 CTAs; CTA jb owns hidden columns j in [jb*8, jb*8+8).
// Computes the 4 gate rows {g*1024 + j} for all 64 batches (GEMM M=64,N=32,K=1024),
// adds gates_x, applies activations, updates c/h, and writes last-hidden.
// h is double-buffered across launches (read g_h[t&1], write g_h[(t+1)&1]).
__global__ __launch_bounds__(256) void lstm_step(
    const float* __restrict__ Whh, const int* __restrict__ lens,
    float* __restrict__ out, int t) {
    __shared__ float h_s[32][68];    // [k][b], padded for float4 alignment
    __shared__ float W_s[32][34];    // [k][n_local], padded for float2 alignment
    __shared__ float pre_s[64][33];  // [b][n_local] pre-activations

    const int tid = threadIdx.x;
    const int j0 = blockIdx.x * 8;
    const int np = tid & 15;          // n-pair index: n_local = 2*np, 2*np+1
    const int b0 = (tid >> 4) * 4;    // 4 batches per thread

    const float* hin = g_h[t & 1];
    float* hout = g_h[(t + 1) & 1];

    ull acc[4] = {0ull, 0ull, 0ull, 0ull};  // packed over n-pair, per batch bb

    for (int k0 = 0; k0 < Hdim; k0 += 32) {
        // load h tile: 64 b x 32 k
#pragma unroll
        for (int q = 0; q < 8; q++) {
            int idx = q * 256 + tid;
            int k = idx & 31;
            int b = idx >> 5;
            h_s[k][b] = hin[b * Hdim + k0 + k];
        }
        // load W tile: 32 rows x 32 k
#pragma unroll
        for (int q = 0; q < 4; q++) {
            int idx = q * 256 + tid;
            int k = idx & 31;
            int nl = idx >> 5;                      // 0..31
            int row = (nl >> 3) * Hdim + j0 + (nl & 7);
            W_s[k][nl] = Whh[(size_t)row * Hdim + k0 + k];
        }
        __syncthreads();
#pragma unroll
        for (int k = 0; k < 32; k++) {
            ull wp = *(const ull*)&W_s[k][np * 2];
            float4 hv = *(const float4*)&h_s[k][b0];
            ull p0 = pack2(hv.x, hv.x);
            ull p1 = pack2(hv.y, hv.y);
            ull p2 = pack2(hv.z, hv.z);
            ull p3 = pack2(hv.w, hv.w);
            ffma2(acc[0], p0, wp);
            ffma2(acc[1], p1, wp);
            ffma2(acc[2], p2, wp);
            ffma2(acc[3], p3, wp);
        }
        __syncthreads();
    }

    // add gates_x and stage pre-activations
    const float* gx_base = g_gates_x + (size_t)(t * Bdim) * Gdim;
#pragma unroll
    for (int bb = 0; bb < 4; bb++) {
        int b = b0 + bb;
        float x, y; unpack2(acc[bb], x, y);
        int n0l = np * 2;
        int n1l = np * 2 + 1;
        int g0row = (n0l >> 3) * Hdim + j0 + (n0l & 7);
        int g1row = (n1l >> 3) * Hdim + j0 + (n1l & 7);
        pre_s[b][n0l] = x + gx_base[(size_t)b * Gdim + g0row];
        pre_s[b][n1l] = y + gx_base[(size_t)b * Gdim + g1row];
    }
    __syncthreads();

    // pointwise LSTM cell update: 512 (b, jj) pairs, 2 per thread
#pragma unroll
    for (int r = 0; r < 2; r++) {
        int p = r * 256 + tid;         // 0..511
        int b = p >> 3;
        int jj = p & 7;
        float xi = pre_s[b][0 + jj];
        float xf = pre_s[b][8 + jj];
        float xg = pre_s[b][16 + jj];
        float xo = pre_s[b][24 + jj];
        float si = sigmoidf_(xi);
        float sf = sigmoidf_(xf);
        float tg = tanhf(xg);
        float so = sigmoidf_(xo);
        int idx = b * Hdim + j0 + jj;
        float c_old = g_c[idx];
        float c_new = sf * c_old + si * tg;
        float h_new = so * tanhf(c_new);
        g_c[idx] = c_new;
        hout[idx] = h_new;
        if (lens[b] > t) out[idx] = h_new;
    }
}

// ---------------- launch ---------------------------------------------------------
extern "C" void kernel_launch(void* const* d_in, const int* in_sizes, int n_in,
                              void* d_out, int out_size) {
    const float* seq  = (const float*)d_in[0];
    const int*   lens = (const int*)d_in[1];
    const float* Wih  = (const float*)d_in[2];
    const float* Whh  = (const float*)d_in[3];
    const float* bih  = (const float*)d_in[4];
    const float* bhh  = (const float*)d_in[5];
    float* out = (float*)d_out;

    init_state<<<256, 256>>>(out);

    dim3 g1(Gdim / 128, (Bdim * Tdim) / 128);
    gates_x_gemm<<<g1, 256>>>(seq, Wih, bih, bhh);

    for (int t = 0; t < Tdim; t++) {
        lstm_step<<<128, 256>>>(Whh, lens, out, t);
    }
}